// round 14
// baseline (speedup 1.0000x reference)
#include <cuda_runtime.h>
#include <math.h>
#include <float.h>

#define NN 100000
#define EE 1600000
#define FH 64
#define FO 40
#define CAP 96   // padded-ELL row capacity; deg ~ Binom(1.6e6,1e-5), mean 16, sd 4

// ---------------- static scratch (no allocations allowed) ----------------
__device__ int   g_cnt[NN];
__device__ int   g_ell[(size_t)NN * CAP];
__device__ float g_agg[(size_t)NN * FH];
__device__ float g_h1[(size_t)NN * FH];
__device__ float g_h2[(size_t)NN * FH];

// ---------------- preprocessing: zero counters, then one-pass ELL build ----------
__global__ void k_zero_cnt() {
    int i = blockIdx.x * blockDim.x + threadIdx.x;
    if (i < NN) g_cnt[i] = 0;
}

__global__ void k_fill_ell(const int* __restrict__ er, const int* __restrict__ ec) {
    int e = blockIdx.x * blockDim.x + threadIdx.x;
    if (e >= EE) return;
    int r = er[e];
    int slot = atomicAdd(&g_cnt[r], 1);
    if (slot < CAP) g_ell[(size_t)r * CAP + slot] = ec[e];
}

// ---------------- aggregation: warp per node, mean over ELL neighbors ----------
__global__ __launch_bounds__(256) void k_agg(const float* __restrict__ act,
                                             float* __restrict__ agg) {
    int w    = (blockIdx.x * blockDim.x + threadIdx.x) >> 5;
    int lane = threadIdx.x & 31;
    if (w >= NN) return;
    int deg = g_cnt[w];
    int e = deg < CAP ? deg : CAP;
    const int* idx = g_ell + (size_t)w * CAP;
    float ax = 0.f, ay = 0.f, bx = 0.f, by = 0.f;
    int i = 0;
    for (; i + 1 < e; i += 2) {
        int j0 = idx[i], j1 = idx[i + 1];
        float2 v0 = *(const float2*)(act + (size_t)j0 * FH + lane * 2);
        float2 v1 = *(const float2*)(act + (size_t)j1 * FH + lane * 2);
        ax += v0.x; ay += v0.y;
        bx += v1.x; by += v1.y;
    }
    if (i < e) {
        int j0 = idx[i];
        float2 v0 = *(const float2*)(act + (size_t)j0 * FH + lane * 2);
        ax += v0.x; ay += v0.y;
    }
    float d = (deg > 0) ? (1.0f / (float)deg) : 0.0f;
    float2 r;
    r.x = (ax + bx) * d;
    r.y = (ay + by) * d;
    *(float2*)(agg + (size_t)w * FH + lane * 2) = r;
}

// ---------------- GEMM: out = A1@W1 + A2@W2 + (b1+b2) ----------------
// BM=64 rows x 64 cols per block, 256 threads, TM=4 x TN=4 (16 acc regs).
// smem: sW 16KB + sA 16KB = 32KB -> ~5 blocks/SM (reg-limited), 40 warps/SM.
// doFinal=1: fused log-softmax over Fo=40 outputs (16-lane shuffle reduction).
__global__ __launch_bounds__(256) void k_gemm(const float* __restrict__ A1,
                                              const float* __restrict__ A2,
                                              const float* __restrict__ W1,
                                              const float* __restrict__ b1,
                                              const float* __restrict__ W2,
                                              const float* __restrict__ b2,
                                              float* __restrict__ out,
                                              int Fo, int doRelu, int doFinal) {
    __shared__ float sW[64][64];
    __shared__ float sA[64][64];

    int tid = threadIdx.x;
    int tx = tid & 15;   // col group: cols tx*4 .. tx*4+3
    int ty = tid >> 4;   // row group: rows ty*4 .. ty*4+3
    int row0 = blockIdx.x * 64;

    float acc[4][4];
#pragma unroll
    for (int i = 0; i < 4; i++)
#pragma unroll
        for (int j = 0; j < 4; j++) acc[i][j] = 0.f;

    for (int pass = 0; pass < 2; ++pass) {
        const float* A = pass ? A2 : A1;
        const float* W = pass ? W2 : W1;
        if (pass) __syncthreads();  // protect smem from previous pass
        // load W (64 x Fo) into sW, zero-padded to 64 cols
        for (int i = tid; i < 64 * 16; i += 256) {
            int r = i >> 4, c4 = (i & 15) * 4;
            float4 v = {0.f, 0.f, 0.f, 0.f};
            if (c4 + 3 < Fo) v = *(const float4*)(W + (size_t)r * Fo + c4);
            *(float4*)&sW[r][c4] = v;
        }
        // load A tile (64 x 64)
        for (int i = tid; i < 64 * 16; i += 256) {
            int r = i >> 4, c4 = (i & 15) * 4;
            int gr = row0 + r;
            float4 v = {0.f, 0.f, 0.f, 0.f};
            if (gr < NN) v = *(const float4*)(A + (size_t)gr * FH + c4);
            *(float4*)&sA[r][c4] = v;
        }
        __syncthreads();
#pragma unroll 4
        for (int k = 0; k < 64; ++k) {
            float4 w = *(const float4*)&sW[k][tx * 4];
#pragma unroll
            for (int i = 0; i < 4; ++i) {
                float a = sA[ty * 4 + i][k];
                acc[i][0] = fmaf(a, w.x, acc[i][0]);
                acc[i][1] = fmaf(a, w.y, acc[i][1]);
                acc[i][2] = fmaf(a, w.z, acc[i][2]);
                acc[i][3] = fmaf(a, w.w, acc[i][3]);
            }
        }
    }

    // bias (neutral for c >= Fo lanes; they don't store)
    int c = tx * 4;
    float bb0 = 0.f, bb1 = 0.f, bb2 = 0.f, bb3 = 0.f;
    if (c < Fo) {
        bb0 = b1[c + 0] + b2[c + 0];
        bb1 = b1[c + 1] + b2[c + 1];
        bb2 = b1[c + 2] + b2[c + 2];
        bb3 = b1[c + 3] + b2[c + 3];
    }

    if (!doFinal) {
        if (c < Fo) {
#pragma unroll
            for (int i = 0; i < 4; ++i) {
                int r = row0 + ty * 4 + i;
                if (r < NN) {
                    float4 v;
                    v.x = acc[i][0] + bb0;
                    v.y = acc[i][1] + bb1;
                    v.z = acc[i][2] + bb2;
                    v.w = acc[i][3] + bb3;
                    if (doRelu) {
                        v.x = fmaxf(v.x, 0.f); v.y = fmaxf(v.y, 0.f);
                        v.z = fmaxf(v.z, 0.f); v.w = fmaxf(v.w, 0.f);
                    }
                    *(float4*)(out + (size_t)r * Fo + c) = v;
                }
            }
        }
    } else {
        // fused log-softmax: 16 lanes sharing ty hold one row's 64 padded cols
        // (40 valid). xor-shuffle 8,4,2,1 stays within the 16-lane group.
        bool valid = (c < Fo);
#pragma unroll
        for (int i = 0; i < 4; ++i) {
            int r = row0 + ty * 4 + i;
            float v0 = acc[i][0] + bb0;
            float v1 = acc[i][1] + bb1;
            float v2 = acc[i][2] + bb2;
            float v3 = acc[i][3] + bb3;
            float m = valid ? fmaxf(fmaxf(v0, v1), fmaxf(v2, v3)) : -FLT_MAX;
#pragma unroll
            for (int o = 8; o > 0; o >>= 1)
                m = fmaxf(m, __shfl_xor_sync(0xFFFFFFFFu, m, o));
            float s = valid ? (__expf(v0 - m) + __expf(v1 - m) +
                               __expf(v2 - m) + __expf(v3 - m)) : 0.f;
#pragma unroll
            for (int o = 8; o > 0; o >>= 1)
                s += __shfl_xor_sync(0xFFFFFFFFu, s, o);
            float ls = m + logf(s);
            if (valid && r < NN) {
                float4 v;
                v.x = v0 - ls; v.y = v1 - ls; v.z = v2 - ls; v.w = v3 - ls;
                *(float4*)(out + (size_t)r * Fo + c) = v;
            }
        }
    }
}

// ---------------- launch ----------------
extern "C" void kernel_launch(void* const* d_in, const int* in_sizes, int n_in,
                              void* d_out, int out_size) {
    const float* x   = (const float*)d_in[0];
    const int*   er  = (const int*)d_in[1];
    const int*   ec  = (const int*)d_in[2];
    const float* Wl0 = (const float*)d_in[5];
    const float* bl0 = (const float*)d_in[6];
    const float* Wr0 = (const float*)d_in[7];
    const float* br0 = (const float*)d_in[8];
    const float* Wl1 = (const float*)d_in[9];
    const float* bl1 = (const float*)d_in[10];
    const float* Wr1 = (const float*)d_in[11];
    const float* br1 = (const float*)d_in[12];
    const float* Wl2 = (const float*)d_in[13];
    const float* bl2 = (const float*)d_in[14];
    const float* Wr2 = (const float*)d_in[15];
    const float* br2 = (const float*)d_in[16];
    float* out = (float*)d_out;

    float* agg; cudaGetSymbolAddress((void**)&agg, g_agg);
    float* h1;  cudaGetSymbolAddress((void**)&h1,  g_h1);
    float* h2;  cudaGetSymbolAddress((void**)&h2,  g_h2);

    // preprocessing: zero counters + one-pass padded-ELL build
    k_zero_cnt<<<(NN + 1023) / 1024, 1024>>>();
    k_fill_ell<<<(EE + 255) / 256, 256>>>(er, ec);

    const int AGG_BLOCKS  = (NN + 7) / 8;        // warp per node, 8 warps per block
    const int GEMM_BLOCKS = (NN + 63) / 64;

    // layer 0   (launch idx: zero=2, fill=3, agg=4, gemm=5 <- ncu -s 5 captures gemm)
    k_agg<<<AGG_BLOCKS, 256>>>(x, agg);
    k_gemm<<<GEMM_BLOCKS, 256>>>(agg, x, Wl0, bl0, Wr0, br0, h1, FH, 1, 0);
    // layer 1
    k_agg<<<AGG_BLOCKS, 256>>>(h1, agg);
    k_gemm<<<GEMM_BLOCKS, 256>>>(agg, h1, Wl1, bl1, Wr1, br1, h2, FH, 1, 0);
    // layer 2: logits + fused log-softmax into d_out
    k_agg<<<AGG_BLOCKS, 256>>>(h2, agg);
    k_gemm<<<GEMM_BLOCKS, 256>>>(agg, h2, Wl2, bl2, Wr2, br2, out, FO, 0, 1);
}

// round 15
// speedup vs baseline: 1.2604x; 1.2604x over previous
#include <cuda_runtime.h>
#include <math.h>
#include <float.h>

#define NN 100000
#define EE 1600000
#define FH 64
#define FO 40
#define CAP 96   // padded-ELL row capacity; deg mean 16, sd 4
#define SST 68   // smem row stride (floats): A-frag loads conflict-free, B 2-way

// ---------------- static scratch (no allocations allowed) ----------------
__device__ int   g_cnt[NN];
__device__ int   g_ell[(size_t)NN * CAP];
__device__ float g_agg[(size_t)NN * FH];
__device__ float g_h1[(size_t)NN * FH];
__device__ float g_h2[(size_t)NN * FH];

// ---------------- preprocessing: zero counters, then one-pass ELL build ----------
__global__ void k_zero_cnt() {
    int i = blockIdx.x * blockDim.x + threadIdx.x;
    if (i < NN) g_cnt[i] = 0;
}

__global__ void k_fill_ell(const int* __restrict__ er, const int* __restrict__ ec) {
    int e = blockIdx.x * blockDim.x + threadIdx.x;
    if (e >= EE) return;
    int r = er[e];
    int slot = atomicAdd(&g_cnt[r], 1);
    if (slot < CAP) g_ell[(size_t)r * CAP + slot] = ec[e];
}

// ---------------- aggregation: warp per node, mean over ELL neighbors [R12 proven] --
__global__ __launch_bounds__(256) void k_agg(const float* __restrict__ act,
                                             float* __restrict__ agg) {
    int w    = (blockIdx.x * blockDim.x + threadIdx.x) >> 5;
    int lane = threadIdx.x & 31;
    if (w >= NN) return;
    int deg = g_cnt[w];
    int e = deg < CAP ? deg : CAP;
    const int* idx = g_ell + (size_t)w * CAP;
    float ax = 0.f, ay = 0.f, bx = 0.f, by = 0.f;
    int i = 0;
    for (; i + 1 < e; i += 2) {
        int j0 = idx[i], j1 = idx[i + 1];
        float2 v0 = *(const float2*)(act + (size_t)j0 * FH + lane * 2);
        float2 v1 = *(const float2*)(act + (size_t)j1 * FH + lane * 2);
        ax += v0.x; ay += v0.y;
        bx += v1.x; by += v1.y;
    }
    if (i < e) {
        int j0 = idx[i];
        float2 v0 = *(const float2*)(act + (size_t)j0 * FH + lane * 2);
        ax += v0.x; ay += v0.y;
    }
    float d = (deg > 0) ? (1.0f / (float)deg) : 0.0f;
    float2 r;
    r.x = (ax + bx) * d;
    r.y = (ay + by) * d;
    *(float2*)(agg + (size_t)w * FH + lane * 2) = r;
}

// ---------------- tf32 helpers ----------------
__device__ __forceinline__ unsigned f2tf(float f) {
    unsigned r;
    asm("cvt.rna.tf32.f32 %0, %1;" : "=r"(r) : "f"(f));
    return r;
}

__device__ __forceinline__ void mma_tf32(float* c, unsigned a0, unsigned a1,
                                         unsigned a2, unsigned a3,
                                         unsigned b0, unsigned b1) {
    asm volatile(
        "mma.sync.aligned.m16n8k8.row.col.f32.tf32.tf32.f32 "
        "{%0,%1,%2,%3}, {%4,%5,%6,%7}, {%8,%9}, {%0,%1,%2,%3};"
        : "+f"(c[0]), "+f"(c[1]), "+f"(c[2]), "+f"(c[3])
        : "r"(a0), "r"(a1), "r"(a2), "r"(a3), "r"(b0), "r"(b1));
}

// ---------------- GEMM: out = A1@W1 + A2@W2 + (b1+b2), tf32 tensor cores ----------
// BM=64 x BN=64 (cols >= Fo masked), 256 threads = 8 warps.
// Warp w: rows (w&3)*16, cols (w>>2)*32 -> 4x m16n8k8 per 8-wide k-step.
// A and W pre-converted to tf32 during smem tile load.
// smem: sA 64x68 + sW 64x68 u32 = 34KB.
__global__ __launch_bounds__(256) void k_gemm(const float* __restrict__ A1,
                                              const float* __restrict__ A2,
                                              const float* __restrict__ W1,
                                              const float* __restrict__ b1,
                                              const float* __restrict__ W2,
                                              const float* __restrict__ b2,
                                              float* __restrict__ out,
                                              int Fo, int doRelu) {
    __shared__ unsigned sA[64 * SST];
    __shared__ unsigned sW[64 * SST];

    int tid  = threadIdx.x;
    int lane = tid & 31;
    int wrp  = tid >> 5;
    int g = lane >> 2;          // group id 0..7
    int t = lane & 3;           // thread-in-group 0..3
    int mrow0 = (wrp & 3) * 16; // warp's row slice
    int ncol0 = (wrp >> 2) * 32;// warp's col half
    int row0 = blockIdx.x * 64;

    float acc[4][4];
#pragma unroll
    for (int i = 0; i < 4; i++)
#pragma unroll
        for (int j = 0; j < 4; j++) acc[i][j] = 0.f;

    for (int pass = 0; pass < 2; ++pass) {
        const float* A = pass ? A2 : A1;
        const float* W = pass ? W2 : W1;
        if (pass) __syncthreads();
        // load + convert W (64 x Fo -> 64 x 64 zero-pad) and A tile (64 x 64)
        for (int i = tid; i < 64 * 16; i += 256) {
            int r = i >> 4, c4 = (i & 15) * 4;
            float4 v = {0.f, 0.f, 0.f, 0.f};
            if (c4 + 3 < Fo) v = *(const float4*)(W + (size_t)r * Fo + c4);
            sW[r * SST + c4 + 0] = f2tf(v.x);
            sW[r * SST + c4 + 1] = f2tf(v.y);
            sW[r * SST + c4 + 2] = f2tf(v.z);
            sW[r * SST + c4 + 3] = f2tf(v.w);
            int gr = row0 + r;
            float4 u = {0.f, 0.f, 0.f, 0.f};
            if (gr < NN) u = *(const float4*)(A + (size_t)gr * FH + c4);
            sA[r * SST + c4 + 0] = f2tf(u.x);
            sA[r * SST + c4 + 1] = f2tf(u.y);
            sA[r * SST + c4 + 2] = f2tf(u.z);
            sA[r * SST + c4 + 3] = f2tf(u.w);
        }
        __syncthreads();
#pragma unroll
        for (int kk = 0; kk < 8; ++kk) {
            int k0 = kk * 8;
            unsigned a0 = sA[(mrow0 + g) * SST + k0 + t];
            unsigned a1 = sA[(mrow0 + g + 8) * SST + k0 + t];
            unsigned a2 = sA[(mrow0 + g) * SST + k0 + t + 4];
            unsigned a3 = sA[(mrow0 + g + 8) * SST + k0 + t + 4];
#pragma unroll
            for (int nt = 0; nt < 4; ++nt) {
                int n0 = ncol0 + nt * 8;
                unsigned b0 = sW[(k0 + t) * SST + n0 + g];
                unsigned b1v = sW[(k0 + t + 4) * SST + n0 + g];
                mma_tf32(acc[nt], a0, a1, a2, a3, b0, b1v);
            }
        }
    }

    // epilogue: bias + optional relu; fragment c: rows g/g+8, cols t*2,t*2+1
    int r0 = row0 + mrow0 + g;
    int r1 = r0 + 8;
#pragma unroll
    for (int nt = 0; nt < 4; ++nt) {
        int cc = ncol0 + nt * 8 + t * 2;
        if (cc < Fo) {           // cc even, Fo even -> cc+1 < Fo too
            float bb0 = b1[cc] + b2[cc];
            float bb1 = b1[cc + 1] + b2[cc + 1];
            float v0 = acc[nt][0] + bb0;
            float v1 = acc[nt][1] + bb1;
            float v2 = acc[nt][2] + bb0;
            float v3 = acc[nt][3] + bb1;
            if (doRelu) {
                v0 = fmaxf(v0, 0.f); v1 = fmaxf(v1, 0.f);
                v2 = fmaxf(v2, 0.f); v3 = fmaxf(v3, 0.f);
            }
            if (r0 < NN) { float2 p = {v0, v1}; *(float2*)(out + (size_t)r0 * Fo + cc) = p; }
            if (r1 < NN) { float2 p = {v2, v3}; *(float2*)(out + (size_t)r1 * Fo + cc) = p; }
        }
    }
}

// ---------------- log-softmax over 40 features, warp per row, in place ----------------
__global__ __launch_bounds__(256) void k_lsm(float* __restrict__ out) {
    int w    = (blockIdx.x * blockDim.x + threadIdx.x) >> 5;
    int lane = threadIdx.x & 31;
    if (w >= NN) return;
    float* p = out + (size_t)w * FO;
    float v0 = p[lane];
    float v1 = (lane < FO - 32) ? p[32 + lane] : -FLT_MAX;
    float m = fmaxf(v0, v1);
#pragma unroll
    for (int o = 16; o > 0; o >>= 1) m = fmaxf(m, __shfl_xor_sync(0xFFFFFFFFu, m, o));
    float s = __expf(v0 - m) + ((lane < FO - 32) ? __expf(v1 - m) : 0.f);
#pragma unroll
    for (int o = 16; o > 0; o >>= 1) s += __shfl_xor_sync(0xFFFFFFFFu, s, o);
    float ls = m + logf(s);
    p[lane] = v0 - ls;
    if (lane < FO - 32) p[32 + lane] = v1 - ls;
}

// ---------------- launch ----------------
extern "C" void kernel_launch(void* const* d_in, const int* in_sizes, int n_in,
                              void* d_out, int out_size) {
    const float* x   = (const float*)d_in[0];
    const int*   er  = (const int*)d_in[1];
    const int*   ec  = (const int*)d_in[2];
    const float* Wl0 = (const float*)d_in[5];
    const float* bl0 = (const float*)d_in[6];
    const float* Wr0 = (const float*)d_in[7];
    const float* br0 = (const float*)d_in[8];
    const float* Wl1 = (const float*)d_in[9];
    const float* bl1 = (const float*)d_in[10];
    const float* Wr1 = (const float*)d_in[11];
    const float* br1 = (const float*)d_in[12];
    const float* Wl2 = (const float*)d_in[13];
    const float* bl2 = (const float*)d_in[14];
    const float* Wr2 = (const float*)d_in[15];
    const float* br2 = (const float*)d_in[16];
    float* out = (float*)d_out;

    float* agg; cudaGetSymbolAddress((void**)&agg, g_agg);
    float* h1;  cudaGetSymbolAddress((void**)&h1,  g_h1);
    float* h2;  cudaGetSymbolAddress((void**)&h2,  g_h2);

    // preprocessing: zero counters + one-pass padded-ELL build
    k_zero_cnt<<<(NN + 1023) / 1024, 1024>>>();
    k_fill_ell<<<(EE + 255) / 256, 256>>>(er, ec);

    const int AGG_BLOCKS  = (NN + 7) / 8;        // warp per node, 8 warps per block
    const int GEMM_BLOCKS = (NN + 63) / 64;

    // layer 0   (launch idx: zero=2, fill=3, agg=4, gemm=5 <- ncu -s 5 captures gemm)
    k_agg<<<AGG_BLOCKS, 256>>>(x, agg);
    k_gemm<<<GEMM_BLOCKS, 256>>>(agg, x, Wl0, bl0, Wr0, br0, h1, FH, 1);
    // layer 1
    k_agg<<<AGG_BLOCKS, 256>>>(h1, agg);
    k_gemm<<<GEMM_BLOCKS, 256>>>(agg, h1, Wl1, bl1, Wr1, br1, h2, FH, 1);
    // layer 2: logits into d_out, then log-softmax in place
    k_agg<<<AGG_BLOCKS, 256>>>(h2, agg);
    k_gemm<<<GEMM_BLOCKS, 256>>>(agg, h2, Wl2, bl2, Wr2, br2, out, FO, 0);
    k_lsm<<<(NN * 32 + 255) / 256, 256>>>(out);
}

// round 17
// speedup vs baseline: 1.2842x; 1.0189x over previous
#include <cuda_runtime.h>
#include <math.h>
#include <float.h>

#define NN 100000
#define EE 1600000
#define FH 64
#define FO 40
#define CAP 96   // padded-ELL row capacity; deg mean 16, sd 4
#define SST 68   // smem row stride (floats): A-frag loads conflict-free, B 2-way

// ---------------- static scratch (no allocations allowed) ----------------
__device__ int   g_cnt[NN];
__device__ int   g_ell[(size_t)NN * CAP];
__device__ float g_agg[(size_t)NN * FH];
__device__ float g_h1[(size_t)NN * FH];
__device__ float g_h2[(size_t)NN * FH];

// ---------------- preprocessing: zero counters, then one-pass ELL build ----------
__global__ void k_zero_cnt() {
    int i = blockIdx.x * blockDim.x + threadIdx.x;
    if (i < NN) g_cnt[i] = 0;
}

__global__ void k_fill_ell(const int* __restrict__ er, const int* __restrict__ ec) {
    int e = blockIdx.x * blockDim.x + threadIdx.x;
    if (e >= EE) return;
    int r = er[e];
    int slot = atomicAdd(&g_cnt[r], 1);
    if (slot < CAP) g_ell[(size_t)r * CAP + slot] = ec[e];
}

// ---------------- aggregation: warp per node, mean over ELL neighbors [R12 proven] --
__global__ __launch_bounds__(256) void k_agg(const float* __restrict__ act,
                                             float* __restrict__ agg) {
    int w    = (blockIdx.x * blockDim.x + threadIdx.x) >> 5;
    int lane = threadIdx.x & 31;
    if (w >= NN) return;
    int deg = g_cnt[w];
    int e = deg < CAP ? deg : CAP;
    const int* idx = g_ell + (size_t)w * CAP;
    float ax = 0.f, ay = 0.f, bx = 0.f, by = 0.f;
    int i = 0;
    for (; i + 1 < e; i += 2) {
        int j0 = idx[i], j1 = idx[i + 1];
        float2 v0 = *(const float2*)(act + (size_t)j0 * FH + lane * 2);
        float2 v1 = *(const float2*)(act + (size_t)j1 * FH + lane * 2);
        ax += v0.x; ay += v0.y;
        bx += v1.x; by += v1.y;
    }
    if (i < e) {
        int j0 = idx[i];
        float2 v0 = *(const float2*)(act + (size_t)j0 * FH + lane * 2);
        ax += v0.x; ay += v0.y;
    }
    float d = (deg > 0) ? (1.0f / (float)deg) : 0.0f;
    float2 r;
    r.x = (ax + bx) * d;
    r.y = (ay + by) * d;
    *(float2*)(agg + (size_t)w * FH + lane * 2) = r;
}

// ---------------- tf32 helpers ----------------
__device__ __forceinline__ unsigned f2tf(float f) {
    unsigned r;
    asm("cvt.rna.tf32.f32 %0, %1;" : "=r"(r) : "f"(f));
    return r;
}

__device__ __forceinline__ uint4 f2tf4(float4 v) {
    uint4 r;
    r.x = f2tf(v.x); r.y = f2tf(v.y); r.z = f2tf(v.z); r.w = f2tf(v.w);
    return r;
}

__device__ __forceinline__ void mma_tf32(float* c, unsigned a0, unsigned a1,
                                         unsigned a2, unsigned a3,
                                         unsigned b0, unsigned b1) {
    asm volatile(
        "mma.sync.aligned.m16n8k8.row.col.f32.tf32.tf32.f32 "
        "{%0,%1,%2,%3}, {%4,%5,%6,%7}, {%8,%9}, {%0,%1,%2,%3};"
        : "+f"(c[0]), "+f"(c[1]), "+f"(c[2]), "+f"(c[3])
        : "r"(a0), "r"(a1), "r"(a2), "r"(a3), "r"(b0), "r"(b1));
}

// ---------------- GEMM: out = A1@W1 + A2@W2 + (b1+b2), tf32 tensor cores ----------
// BM=64 x BN=64 (cols >= Fo masked), 256 threads = 8 warps.
// Warp w: rows (w&3)*16, cols (w>>2)*32 -> 4x m16n8k8 per 8-wide k-step.
// Tile load: LDG.128 -> f2tf x4 -> one STS.128 (was 4x STS.32 -> L1-bound).
// smem: sA 64x68 + sW 64x68 u32 = 34KB.
__global__ __launch_bounds__(256) void k_gemm(const float* __restrict__ A1,
                                              const float* __restrict__ A2,
                                              const float* __restrict__ W1,
                                              const float* __restrict__ b1,
                                              const float* __restrict__ W2,
                                              const float* __restrict__ b2,
                                              float* __restrict__ out,
                                              int Fo, int doRelu) {
    __shared__ unsigned sA[64 * SST];
    __shared__ unsigned sW[64 * SST];

    int tid  = threadIdx.x;
    int lane = tid & 31;
    int wrp  = tid >> 5;
    int g = lane >> 2;          // group id 0..7
    int t = lane & 3;           // thread-in-group 0..3
    int mrow0 = (wrp & 3) * 16; // warp's row slice
    int ncol0 = (wrp >> 2) * 32;// warp's col half
    int row0 = blockIdx.x * 64;

    float acc[4][4];
#pragma unroll
    for (int i = 0; i < 4; i++)
#pragma unroll
        for (int j = 0; j < 4; j++) acc[i][j] = 0.f;

    for (int pass = 0; pass < 2; ++pass) {
        const float* A = pass ? A2 : A1;
        const float* W = pass ? W2 : W1;
        if (pass) __syncthreads();
        // load + convert W (64 x Fo -> 64 x 64 zero-pad) and A tile (64 x 64),
        // vectorized STS.128
        for (int i = tid; i < 64 * 16; i += 256) {
            int r = i >> 4, c4 = (i & 15) * 4;
            float4 v = {0.f, 0.f, 0.f, 0.f};
            if (c4 + 3 < Fo) v = *(const float4*)(W + (size_t)r * Fo + c4);
            *(uint4*)&sW[r * SST + c4] = f2tf4(v);
            int gr = row0 + r;
            float4 u = {0.f, 0.f, 0.f, 0.f};
            if (gr < NN) u = *(const float4*)(A + (size_t)gr * FH + c4);
            *(uint4*)&sA[r * SST + c4] = f2tf4(u);
        }
        __syncthreads();
#pragma unroll
        for (int kk = 0; kk < 8; ++kk) {
            int k0 = kk * 8;
            unsigned a0 = sA[(mrow0 + g) * SST + k0 + t];
            unsigned a1 = sA[(mrow0 + g + 8) * SST + k0 + t];
            unsigned a2 = sA[(mrow0 + g) * SST + k0 + t + 4];
            unsigned a3 = sA[(mrow0 + g + 8) * SST + k0 + t + 4];
#pragma unroll
            for (int nt = 0; nt < 4; ++nt) {
                int n0 = ncol0 + nt * 8;
                unsigned b0 = sW[(k0 + t) * SST + n0 + g];
                unsigned b1v = sW[(k0 + t + 4) * SST + n0 + g];
                mma_tf32(acc[nt], a0, a1, a2, a3, b0, b1v);
            }
        }
    }

    // epilogue: bias + optional relu; fragment c: rows g/g+8, cols t*2,t*2+1
    int r0 = row0 + mrow0 + g;
    int r1 = r0 + 8;
#pragma unroll
    for (int nt = 0; nt < 4; ++nt) {
        int cc = ncol0 + nt * 8 + t * 2;
        if (cc < Fo) {           // cc even, Fo even -> cc+1 < Fo too
            float bb0 = b1[cc] + b2[cc];
            float bb1 = b1[cc + 1] + b2[cc + 1];
            float v0 = acc[nt][0] + bb0;
            float v1 = acc[nt][1] + bb1;
            float v2 = acc[nt][2] + bb0;
            float v3 = acc[nt][3] + bb1;
            if (doRelu) {
                v0 = fmaxf(v0, 0.f); v1 = fmaxf(v1, 0.f);
                v2 = fmaxf(v2, 0.f); v3 = fmaxf(v3, 0.f);
            }
            if (r0 < NN) { float2 p = {v0, v1}; *(float2*)(out + (size_t)r0 * Fo + cc) = p; }
            if (r1 < NN) { float2 p = {v2, v3}; *(float2*)(out + (size_t)r1 * Fo + cc) = p; }
        }
    }
}

// ---------------- log-softmax over 40 features, warp per row, in place ----------------
__global__ __launch_bounds__(256) void k_lsm(float* __restrict__ out) {
    int w    = (blockIdx.x * blockDim.x + threadIdx.x) >> 5;
    int lane = threadIdx.x & 31;
    if (w >= NN) return;
    float* p = out + (size_t)w * FO;
    float v0 = p[lane];
    float v1 = (lane < FO - 32) ? p[32 + lane] : -FLT_MAX;
    float m = fmaxf(v0, v1);
#pragma unroll
    for (int o = 16; o > 0; o >>= 1) m = fmaxf(m, __shfl_xor_sync(0xFFFFFFFFu, m, o));
    float s = __expf(v0 - m) + ((lane < FO - 32) ? __expf(v1 - m) : 0.f);
#pragma unroll
    for (int o = 16; o > 0; o >>= 1) s += __shfl_xor_sync(0xFFFFFFFFu, s, o);
    float ls = m + logf(s);
    p[lane] = v0 - ls;
    if (lane < FO - 32) p[32 + lane] = v1 - ls;
}

// ---------------- launch ----------------
extern "C" void kernel_launch(void* const* d_in, const int* in_sizes, int n_in,
                              void* d_out, int out_size) {
    const float* x   = (const float*)d_in[0];
    const int*   er  = (const int*)d_in[1];
    const int*   ec  = (const int*)d_in[2];
    const float* Wl0 = (const float*)d_in[5];
    const float* bl0 = (const float*)d_in[6];
    const float* Wr0 = (const float*)d_in[7];
    const float* br0 = (const float*)d_in[8];
    const float* Wl1 = (const float*)d_in[9];
    const float* bl1 = (const float*)d_in[10];
    const float* Wr1 = (const float*)d_in[11];
    const float* br1 = (const float*)d_in[12];
    const float* Wl2 = (const float*)d_in[13];
    const float* bl2 = (const float*)d_in[14];
    const float* Wr2 = (const float*)d_in[15];
    const float* br2 = (const float*)d_in[16];
    float* out = (float*)d_out;

    float* agg; cudaGetSymbolAddress((void**)&agg, g_agg);
    float* h1;  cudaGetSymbolAddress((void**)&h1,  g_h1);
    float* h2;  cudaGetSymbolAddress((void**)&h2,  g_h2);

    // preprocessing: zero counters + one-pass padded-ELL build
    k_zero_cnt<<<(NN + 1023) / 1024, 1024>>>();
    k_fill_ell<<<(EE + 255) / 256, 256>>>(er, ec);

    const int AGG_BLOCKS  = (NN + 7) / 8;        // warp per node, 8 warps per block
    const int GEMM_BLOCKS = (NN + 63) / 64;

    // layer 0   (launch idx: zero=2, fill=3, agg=4, gemm=5 <- ncu -s 5 captures gemm)
    k_agg<<<AGG_BLOCKS, 256>>>(x, agg);
    k_gemm<<<GEMM_BLOCKS, 256>>>(agg, x, Wl0, bl0, Wr0, br0, h1, FH, 1);
    // layer 1
    k_agg<<<AGG_BLOCKS, 256>>>(h1, agg);
    k_gemm<<<GEMM_BLOCKS, 256>>>(agg, h1, Wl1, bl1, Wr1, br1, h2, FH, 1);
    // layer 2: logits into d_out, then log-softmax in place
    k_agg<<<AGG_BLOCKS, 256>>>(h2, agg);
    k_gemm<<<GEMM_BLOCKS, 256>>>(agg, h2, Wl2, bl2, Wr2, br2, out, FO, 0);
    k_lsm<<<(NN * 32 + 255) / 256, 256>>>(out);
}